// round 2
// baseline (speedup 1.0000x reference)
#include <cuda_runtime.h>

// Pooled attention embedding bag:
//   B=8192 bags, L=50 items/bag (generic via offsets), D=64, ATT=64, K=4.
//   out[b,k,:] = sum_i softmax_i( tanh(E_i @ Wp^T + b) @ att_h )[k] * E_i
//
// One CTA per bag; operands staged in smem with row pad 68 (16B-aligned rows,
// conflict-free strided access). Index dtype (int32 vs int64) is detected
// on-device because JAX commonly downcasts int64 -> int32.

namespace {
constexpr int Dm    = 64;   // embedding dim
constexpr int ATTm  = 64;   // attention dim
constexpr int KN    = 4;    // acc_user_num
constexpr int MAXI  = 64;   // max items per bag staged in smem (dataset: 50)
constexpr int PAD   = 68;   // padded row length (floats)
constexpr int NT    = 256;  // threads per block
constexpr int SMEM_FLOATS = 64*PAD      // Wt  [d][a]
                          + MAXI*PAD    // E   [i][d]
                          + MAXI*PAD    // H   [i][a]
                          + MAXI*KN     // att [i][k]
                          + ATTm*KN     // att_h
                          + ATTm        // proj_b
                          + 8;          // reductions
}

__device__ int g_idx_is64;   // 1 if index/offset buffers are int64, else int32

__device__ __forceinline__ float tanh_fast(float x) {
    float y;
    asm("tanh.approx.f32 %0, %1;" : "=f"(y) : "f"(x));
    return y;
}

__device__ __forceinline__ long long ld_idx(const void* p, long long i, int is64) {
    return is64 ? ((const long long*)p)[i]
                : (long long)((const int*)p)[i];
}

// One thread: decide whether the int64 interpretation of offsets/input_ is
// self-consistent. int32 data read as int64 packs two values per word and
// fails the range/monotonicity checks deterministically.
extern "C" __global__ void detect_idx_dtype(const void* __restrict__ input_,
                                            const void* __restrict__ offsets,
                                            long long nnz, int nseg,
                                            long long vocab) {
    bool ok = true;
    const long long* o64 = (const long long*)offsets;
    int no = nseg < 4 ? nseg : 4;
    long long prev = -1;
    for (int i = 0; i < no; ++i) {          // reads <= 32B; safe for either dtype
        long long v = o64[i];
        if (v < 0 || v > nnz || v < prev) ok = false;
        prev = v;
    }
    const long long* in64 = (const long long*)input_;
    long long ni = nnz < 8 ? nnz : 8;       // reads <= 64B; safe for either dtype
    for (long long i = 0; i < ni; ++i) {
        long long v = in64[i];
        if (v < 0 || v >= vocab) ok = false;
    }
    g_idx_is64 = ok ? 1 : 0;
}

extern "C" __global__ void __launch_bounds__(NT, 4)
pooled_att_kernel(const void*  __restrict__ input_,
                  const void*  __restrict__ offsets,
                  const float* __restrict__ emb,
                  const float* __restrict__ projw,   // [ATT, D] row-major
                  const float* __restrict__ projb,   // [ATT]
                  const float* __restrict__ atth,    // [ATT, K] row-major
                  float*       __restrict__ out,     // [B, K, D]
                  int nseg, long long nnz)
{
    extern __shared__ float sm[];
    float* Wt  = sm;                    // [64][PAD]  Wt[d*PAD+a] = projw[a*64+d]
    float* E   = Wt  + 64*PAD;          // [MAXI][PAD]
    float* Hs  = E   + MAXI*PAD;        // [MAXI][PAD]
    float* At  = Hs  + MAXI*PAD;        // [MAXI][KN]
    float* Ah  = At  + MAXI*KN;         // [ATT][KN]
    float* Pb  = Ah  + ATTm*KN;         // [ATT]
    float* Red = Pb  + ATTm;            // [8]: 0..3 = colmax, 4..7 = 1/sum

    const int tid  = threadIdx.x;
    const int bag  = blockIdx.x;
    const int is64 = g_idx_is64;

    const long long start = ld_idx(offsets, bag, is64);
    const long long end   = (bag + 1 < nseg) ? ld_idx(offsets, bag + 1, is64) : nnz;
    int count = (int)(end - start);
    if (count > MAXI) count = MAXI;
    if (count < 0)    count = 0;

    // ---- stage weights (transpose proj_w into Wt[d][a]) ----
    for (int p = tid; p < 64 * 64; p += NT) {
        int a = p >> 6, d = p & 63;          // coalesced global read of projw
        Wt[d * PAD + a] = projw[p];
    }
    for (int p = tid; p < ATTm * KN; p += NT) Ah[p] = atth[p];
    if (tid < ATTm) Pb[tid] = projb[tid];

    // ---- gather embeddings into E (float4, 16 threads/row) ----
    const int nIT  = (count + 3) >> 2;       // 4-item tiles
    const int rows = nIT << 2;
    {
        const int c = tid & 15;              // which float4 of the 64-float row
        for (int i = tid >> 4; i < rows; i += NT / 16) {
            float4 v = make_float4(0.f, 0.f, 0.f, 0.f);
            if (i < count) {
                long long idx = ld_idx(input_, start + i, is64);
                v = reinterpret_cast<const float4*>(emb + idx * (long long)Dm)[c];
            }
            reinterpret_cast<float4*>(E + i * PAD)[c] = v;
        }
    }
    __syncthreads();

    // ---- H = tanh(E @ Wt + b): 4 items x 4 att-features per thread ----
    const int nTiles = nIT * 16;             // 16 a-tiles of width 4
    for (int t = tid; t < nTiles; t += NT) {
        const int ta = t & 15;               // a-tile (fastest within warp)
        const int ti = t >> 4;               // item tile
        const int a0 = ta << 2;
        const int i0 = ti << 2;

        float acc[4][4];
        {
            float4 pb4 = *reinterpret_cast<float4*>(Pb + a0);
            #pragma unroll
            for (int r = 0; r < 4; ++r) {
                acc[r][0] = pb4.x; acc[r][1] = pb4.y;
                acc[r][2] = pb4.z; acc[r][3] = pb4.w;
            }
        }
        const float* ep = E + i0 * PAD;
        #pragma unroll 16
        for (int d = 0; d < 64; ++d) {
            float4 w = *reinterpret_cast<float4*>(Wt + d * PAD + a0);
            float e0 = ep[d];
            float e1 = ep[PAD + d];
            float e2 = ep[2 * PAD + d];
            float e3 = ep[3 * PAD + d];
            acc[0][0] += e0 * w.x; acc[0][1] += e0 * w.y; acc[0][2] += e0 * w.z; acc[0][3] += e0 * w.w;
            acc[1][0] += e1 * w.x; acc[1][1] += e1 * w.y; acc[1][2] += e1 * w.z; acc[1][3] += e1 * w.w;
            acc[2][0] += e2 * w.x; acc[2][1] += e2 * w.y; acc[2][2] += e2 * w.z; acc[2][3] += e2 * w.w;
            acc[3][0] += e3 * w.x; acc[3][1] += e3 * w.y; acc[3][2] += e3 * w.z; acc[3][3] += e3 * w.w;
        }
        #pragma unroll
        for (int r = 0; r < 4; ++r) {
            float4 h;
            h.x = tanh_fast(acc[r][0]);
            h.y = tanh_fast(acc[r][1]);
            h.z = tanh_fast(acc[r][2]);
            h.w = tanh_fast(acc[r][3]);
            *reinterpret_cast<float4*>(Hs + (i0 + r) * PAD + a0) = h;
        }
    }
    __syncthreads();

    // ---- att[i][k] = H[i,:] @ att_h[:,k] ----
    for (int t = tid; t < count * KN; t += NT) {
        const int i = t >> 2, k = t & 3;
        const float* hp = Hs + i * PAD;
        float acc = 0.f;
        #pragma unroll 8
        for (int a = 0; a < ATTm; ++a) acc += hp[a] * Ah[a * KN + k];
        At[t] = acc;
    }
    __syncthreads();

    // ---- ragged softmax over items, per column k ----
    if (tid < KN) {
        float m = -1e30f;
        for (int i = 0; i < count; ++i) m = fmaxf(m, At[i * KN + tid]);
        Red[tid] = m;
    }
    __syncthreads();
    for (int t = tid; t < count * KN; t += NT)
        At[t] = __expf(At[t] - Red[t & 3]);
    __syncthreads();
    if (tid < KN) {
        float s = 0.f;
        for (int i = 0; i < count; ++i) s += At[i * KN + tid];
        Red[4 + tid] = 1.0f / s;
    }
    __syncthreads();

    // ---- pooled output: thread = (k, d); coalesced 256-float store per bag ----
    {
        const int k = tid >> 6;
        const int d = tid & 63;
        float acc = 0.f;
        for (int i = 0; i < count; ++i)
            acc += At[i * KN + k] * E[i * PAD + d];
        out[(size_t)bag * (KN * Dm) + tid] = acc * Red[4 + k];
    }
}

extern "C" void kernel_launch(void* const* d_in, const int* in_sizes, int n_in,
                              void* d_out, int out_size) {
    const void*  input_  = d_in[0];
    const void*  offsets = d_in[1];
    const float* emb     = (const float*)d_in[2];
    const float* projw   = (const float*)d_in[3];
    const float* projb   = (const float*)d_in[4];
    const float* atth    = (const float*)d_in[5];
    float* out = (float*)d_out;

    const int       nseg  = in_sizes[1];
    const long long nnz   = in_sizes[0];
    const long long vocab = (long long)in_sizes[2] / Dm;

    detect_idx_dtype<<<1, 1>>>(input_, offsets, nnz, nseg, vocab);

    const size_t smem = SMEM_FLOATS * sizeof(float);  // ~54.6 KB
    cudaFuncSetAttribute(pooled_att_kernel,
                         cudaFuncAttributeMaxDynamicSharedMemorySize, (int)smem);
    pooled_att_kernel<<<nseg, NT, smem>>>(input_, offsets, emb, projw, projb,
                                          atth, out, nseg, nnz);
}

// round 3
// speedup vs baseline: 1.0627x; 1.0627x over previous
#include <cuda_runtime.h>

// Pooled attention embedding bag:
//   B=8192 bags, L=50 items/bag (generic via offsets), D=64, ATT=64, K=4.
//   out[b,k,:] = sum_i softmax_i( tanh(E_i @ Wp^T + b) @ att_h )[k] * E_i
//
// One CTA per bag; operands staged in smem with row pad 68 (16B-aligned rows,
// conflict-free strided access). Main GEMM uses float4/double2 LDS.128 for
// both operands and packed fma.rn.f32x2 (Blackwell) accumulation.
// Index dtype (int32 vs int64) is detected on-device (JAX downcasts int64).

namespace {
constexpr int Dm    = 64;   // embedding dim
constexpr int ATTm  = 64;   // attention dim
constexpr int KN    = 4;    // acc_user_num
constexpr int MAXI  = 64;   // max items per bag staged in smem (dataset: 50)
constexpr int PAD   = 68;   // padded row length (floats): rows 16B aligned
constexpr int NT    = 256;  // threads per block
constexpr int SMEM_FLOATS = 64*PAD      // Wt  [d][a]
                          + MAXI*PAD    // E   [i][d]
                          + MAXI*PAD    // H   [i][a]
                          + MAXI*KN     // att [i][k]
                          + KN*PAD      // AhT [k][a]
                          + ATTm        // proj_b
                          + 8;          // reductions
}

__device__ int g_idx_is64;   // 1 if index/offset buffers are int64, else int32

using ull = unsigned long long;

__device__ __forceinline__ float tanh_fast(float x) {
    float y;
    asm("tanh.approx.f32 %0, %1;" : "=f"(y) : "f"(x));
    return y;
}

// packed dual-FMA: d.lo += a.lo*b.lo ; d.hi += a.hi*b.hi  (bit-exact fp32)
__device__ __forceinline__ void ffma2(ull& d, ull a, ull b) {
    asm("fma.rn.f32x2 %0, %1, %2, %0;" : "+l"(d) : "l"(a), "l"(b));
}
__device__ __forceinline__ ull bcast2(float x) {
    ull r;
    asm("mov.b64 %0, {%1, %1};" : "=l"(r) : "f"(x));
    return r;
}
__device__ __forceinline__ void unpack2(float& lo, float& hi, ull v) {
    asm("mov.b64 {%0, %1}, %2;" : "=f"(lo), "=f"(hi) : "l"(v));
}

__device__ __forceinline__ long long ld_idx(const void* p, long long i, int is64) {
    return is64 ? ((const long long*)p)[i]
                : (long long)((const int*)p)[i];
}

// One thread: decide whether the int64 interpretation of offsets/input_ is
// self-consistent. int32 data read as int64 fails range/monotonicity checks.
extern "C" __global__ void detect_idx_dtype(const void* __restrict__ input_,
                                            const void* __restrict__ offsets,
                                            long long nnz, int nseg,
                                            long long vocab) {
    bool ok = true;
    const long long* o64 = (const long long*)offsets;
    int no = nseg < 4 ? nseg : 4;
    long long prev = -1;
    for (int i = 0; i < no; ++i) {
        long long v = o64[i];
        if (v < 0 || v > nnz || v < prev) ok = false;
        prev = v;
    }
    const long long* in64 = (const long long*)input_;
    long long ni = nnz < 8 ? nnz : 8;
    for (long long i = 0; i < ni; ++i) {
        long long v = in64[i];
        if (v < 0 || v >= vocab) ok = false;
    }
    g_idx_is64 = ok ? 1 : 0;
}

extern "C" __global__ void __launch_bounds__(NT, 3)
pooled_att_kernel(const void*  __restrict__ input_,
                  const void*  __restrict__ offsets,
                  const float* __restrict__ emb,
                  const float* __restrict__ projw,   // [ATT, D] row-major
                  const float* __restrict__ projb,   // [ATT]
                  const float* __restrict__ atth,    // [ATT, K] row-major
                  float*       __restrict__ out,     // [B, K, D]
                  int nseg, long long nnz)
{
    extern __shared__ float sm[];
    float* Wt  = sm;                    // [64][PAD]  Wt[d*PAD+a] = projw[a*64+d]
    float* E   = Wt  + 64*PAD;          // [MAXI][PAD]
    float* Hs  = E   + MAXI*PAD;        // [MAXI][PAD]
    float* At  = Hs  + MAXI*PAD;        // [MAXI][KN]
    float* AhT = At  + MAXI*KN;         // [KN][PAD]  AhT[k][a] = atth[a*KN+k]
    float* Pb  = AhT + KN*PAD;          // [ATT]
    float* Red = Pb  + ATTm;            // [8]: 0..3 = colmax, 4..7 = 1/sum

    const int tid  = threadIdx.x;
    const int bag  = blockIdx.x;
    const int is64 = g_idx_is64;

    const long long start = ld_idx(offsets, bag, is64);
    const long long end   = (bag + 1 < nseg) ? ld_idx(offsets, bag + 1, is64) : nnz;
    int count = (int)(end - start);
    if (count > MAXI) count = MAXI;
    if (count < 0)    count = 0;

    // ---- stage weights (transpose proj_w into Wt[d][a], atth into AhT[k][a]) ----
    for (int p = tid; p < 64 * 64; p += NT) {
        int a = p >> 6, d = p & 63;          // coalesced global read of projw
        Wt[d * PAD + a] = projw[p];
    }
    if (tid < ATTm * KN) {
        int a = tid >> 2, k = tid & 3;
        AhT[k * PAD + a] = atth[tid];
    }
    if (tid < ATTm) Pb[tid] = projb[tid];

    // ---- gather embeddings into E (float4, 16 threads/row) ----
    const int nIT  = (count + 3) >> 2;       // 4-item tiles
    const int rows = nIT << 2;
    {
        const int c = tid & 15;              // which float4 of the 64-float row
        for (int i = tid >> 4; i < rows; i += NT / 16) {
            float4 v = make_float4(0.f, 0.f, 0.f, 0.f);
            if (i < count) {
                long long idx = ld_idx(input_, start + i, is64);
                v = reinterpret_cast<const float4*>(emb + idx * (long long)Dm)[c];
            }
            reinterpret_cast<float4*>(E + i * PAD)[c] = v;
        }
    }
    __syncthreads();

    // ---- H = tanh(E @ Wt + b): 4 items x 4 att-features per thread ----
    // All smem traffic via LDS.128; accumulation via packed fma.rn.f32x2.
    const int nTiles = nIT * 16;             // 16 a-tiles of width 4
    for (int t = tid; t < nTiles; t += NT) {
        const int ta = t & 15;               // a-tile (fastest within warp)
        const int ti = t >> 4;               // item tile
        const int a0 = ta << 2;
        const int i0 = ti << 2;

        ull acc[4][2];
        {
            double2 pbv = *reinterpret_cast<const double2*>(Pb + a0);
            ull plo = __double_as_longlong(pbv.x);
            ull phi = __double_as_longlong(pbv.y);
            #pragma unroll
            for (int r = 0; r < 4; ++r) { acc[r][0] = plo; acc[r][1] = phi; }
        }
        const float* ep = E + i0 * PAD;
        #pragma unroll 4
        for (int d = 0; d < 64; d += 4) {
            double2 w0 = *reinterpret_cast<const double2*>(Wt + (d+0)*PAD + a0);
            double2 w1 = *reinterpret_cast<const double2*>(Wt + (d+1)*PAD + a0);
            double2 w2 = *reinterpret_cast<const double2*>(Wt + (d+2)*PAD + a0);
            double2 w3 = *reinterpret_cast<const double2*>(Wt + (d+3)*PAD + a0);
            const ull w0l = __double_as_longlong(w0.x), w0h = __double_as_longlong(w0.y);
            const ull w1l = __double_as_longlong(w1.x), w1h = __double_as_longlong(w1.y);
            const ull w2l = __double_as_longlong(w2.x), w2h = __double_as_longlong(w2.y);
            const ull w3l = __double_as_longlong(w3.x), w3h = __double_as_longlong(w3.y);
            #pragma unroll
            for (int r = 0; r < 4; ++r) {
                float4 e = *reinterpret_cast<const float4*>(ep + r * PAD + d);
                const ull ex = bcast2(e.x), ey = bcast2(e.y);
                const ull ez = bcast2(e.z), ew = bcast2(e.w);
                ffma2(acc[r][0], ex, w0l); ffma2(acc[r][1], ex, w0h);
                ffma2(acc[r][0], ey, w1l); ffma2(acc[r][1], ey, w1h);
                ffma2(acc[r][0], ez, w2l); ffma2(acc[r][1], ez, w2h);
                ffma2(acc[r][0], ew, w3l); ffma2(acc[r][1], ew, w3h);
            }
        }
        #pragma unroll
        for (int r = 0; r < 4; ++r) {
            float h0, h1, h2, h3;
            unpack2(h0, h1, acc[r][0]);
            unpack2(h2, h3, acc[r][1]);
            float4 h;
            h.x = tanh_fast(h0); h.y = tanh_fast(h1);
            h.z = tanh_fast(h2); h.w = tanh_fast(h3);
            *reinterpret_cast<float4*>(Hs + (i0 + r) * PAD + a0) = h;
        }
    }
    __syncthreads();

    // ---- att[i][k] = H[i,:] @ att_h[:,k]  (float4 dot products) ----
    for (int t = tid; t < count * KN; t += NT) {
        const int i = t >> 2, k = t & 3;
        const float4* hp = reinterpret_cast<const float4*>(Hs + i * PAD);
        const float4* ap = reinterpret_cast<const float4*>(AhT + k * PAD);
        float acc = 0.f;
        #pragma unroll
        for (int a4 = 0; a4 < ATTm / 4; ++a4) {
            float4 h = hp[a4];
            float4 a = ap[a4];
            acc += h.x * a.x + h.y * a.y + h.z * a.z + h.w * a.w;
        }
        At[t] = acc;
    }
    __syncthreads();

    // ---- ragged softmax over items, per column k ----
    if (tid < KN) {
        float m = -1e30f;
        for (int i = 0; i < count; ++i) m = fmaxf(m, At[i * KN + tid]);
        Red[tid] = m;
    }
    __syncthreads();
    for (int t = tid; t < count * KN; t += NT)
        At[t] = __expf(At[t] - Red[t & 3]);
    __syncthreads();
    if (tid < KN) {
        float s = 0.f;
        for (int i = 0; i < count; ++i) s += At[i * KN + tid];
        Red[4 + tid] = 1.0f / s;
    }
    __syncthreads();

    // ---- pooled output: thread = (k, d); coalesced 256-float store per bag ----
    {
        const int k = tid >> 6;
        const int d = tid & 63;
        float acc = 0.f;
        for (int i = 0; i < count; ++i)
            acc += At[i * KN + k] * E[i * PAD + d];
        out[(size_t)bag * (KN * Dm) + tid] = acc * Red[4 + k];
    }
}

extern "C" void kernel_launch(void* const* d_in, const int* in_sizes, int n_in,
                              void* d_out, int out_size) {
    const void*  input_  = d_in[0];
    const void*  offsets = d_in[1];
    const float* emb     = (const float*)d_in[2];
    const float* projw   = (const float*)d_in[3];
    const float* projb   = (const float*)d_in[4];
    const float* atth    = (const float*)d_in[5];
    float* out = (float*)d_out;

    const int       nseg  = in_sizes[1];
    const long long nnz   = in_sizes[0];
    const long long vocab = (long long)in_sizes[2] / Dm;

    detect_idx_dtype<<<1, 1>>>(input_, offsets, nnz, nseg, vocab);

    const size_t smem = SMEM_FLOATS * sizeof(float);  // ~54.7 KB
    cudaFuncSetAttribute(pooled_att_kernel,
                         cudaFuncAttributeMaxDynamicSharedMemorySize, (int)smem);
    pooled_att_kernel<<<nseg, NT, smem>>>(input_, offsets, emb, projw, projb,
                                          atth, out, nseg, nnz);
}